// round 1
// baseline (speedup 1.0000x reference)
#include <cuda_runtime.h>
#include <cuda_bf16.h>
#include <math.h>

#define T_NEW 16
#define HIDDEN 2560
#define INTER 9728
#define N_HEADS 32
#define N_KV 8
#define HD 128
#define T_CACHE 4080
#define SEQ 4096
#define RMS_EPS 1e-6f

// ---------------- scratch ----------------
__device__ float g_y[T_NEW * HIDDEN];
__device__ float g_q[T_NEW * N_HEADS * HD];
__device__ float g_k[T_NEW * N_KV * HD];
__device__ float g_v[T_NEW * N_KV * HD];
__device__ float g_knew[N_KV * T_NEW * HD];
__device__ float g_vnew[N_KV * T_NEW * HD];
__device__ float g_scores[N_HEADS * T_NEW * SEQ];
__device__ float g_attn[T_NEW * N_HEADS * HD];
__device__ float g_h[T_NEW * HIDDEN];
__device__ float g_y2[T_NEW * HIDDEN];
__device__ float g_gate[T_NEW * INTER];
__device__ float g_up[T_NEW * INTER];
__device__ float g_act[T_NEW * INTER];

// ---------------- rmsnorm over K (K=2560), grid = T_NEW, 256 thr ----------------
__global__ void rmsnorm_kernel(const float* __restrict__ x, const float* __restrict__ w,
                               float* __restrict__ y, int K) {
    int t = blockIdx.x;
    const float* xr = x + (size_t)t * K;
    float vals[10];
    float ss = 0.f;
    int n = 0;
    for (int i = threadIdx.x; i < K; i += 256, n++) {
        float v = xr[i];
        vals[n] = v;
        ss += v * v;
    }
    __shared__ float sred[8];
    __shared__ float stot;
    #pragma unroll
    for (int o = 16; o; o >>= 1) ss += __shfl_down_sync(0xffffffffu, ss, o);
    int lane = threadIdx.x & 31, wid = threadIdx.x >> 5;
    if (lane == 0) sred[wid] = ss;
    __syncthreads();
    if (threadIdx.x == 0) {
        float tot = 0.f;
        for (int i = 0; i < 8; i++) tot += sred[i];
        stot = tot;
    }
    __syncthreads();
    float r = rsqrtf(stot / (float)K + RMS_EPS);
    n = 0;
    for (int i = threadIdx.x; i < K; i += 256, n++) {
        y[(size_t)t * K + i] = vals[n] * r * w[i];
    }
}

// ---------------- GEMV over 16 tokens: out[t][row] = Y[t]·W[row] (+res) ----------------
// 256 threads. Block handles R = 8*rpw rows. Activations chunked into SMEM.
__global__ void gemm16_kernel(const float* __restrict__ W, const float* __restrict__ Y,
                              float* __restrict__ out, const float* __restrict__ res,
                              int K, int KC, int n_rows, int rpw) {
    extern __shared__ float sm[];
    float* ysh = sm;                  // 16 * KC
    float* accs = sm + 16 * KC;       // R * 16
    int R = 8 * rpw;
    int r0 = blockIdx.x * R;
    int tid = threadIdx.x, lane = tid & 31, wid = tid >> 5;
    for (int i = tid; i < R * 16; i += 256) accs[i] = 0.f;
    int KC4 = KC >> 2;
    for (int c0 = 0; c0 < K; c0 += KC) {
        __syncthreads();
        for (int idx = tid; idx < 16 * KC4; idx += 256) {
            int t = idx / KC4, i = idx - t * KC4;
            reinterpret_cast<float4*>(ysh + t * KC)[i] =
                reinterpret_cast<const float4*>(Y + (size_t)t * K + c0)[i];
        }
        __syncthreads();
        for (int rr = 0; rr < rpw; rr++) {
            int row = r0 + wid * rpw + rr;
            const float4* w4 = reinterpret_cast<const float4*>(W + (size_t)row * K + c0);
            float a[16];
            #pragma unroll
            for (int t = 0; t < 16; t++) a[t] = 0.f;
            for (int i = lane; i < KC4; i += 32) {
                float4 w = w4[i];
                #pragma unroll
                for (int t = 0; t < 16; t++) {
                    float4 yv = reinterpret_cast<const float4*>(ysh + t * KC)[i];
                    a[t] += w.x * yv.x + w.y * yv.y + w.z * yv.z + w.w * yv.w;
                }
            }
            #pragma unroll
            for (int t = 0; t < 16; t++) {
                float v = a[t];
                #pragma unroll
                for (int o = 16; o; o >>= 1) v += __shfl_down_sync(0xffffffffu, v, o);
                if (lane == 0) accs[(wid * rpw + rr) * 16 + t] += v;
            }
        }
    }
    __syncthreads();
    for (int idx = tid; idx < R * 16; idx += 256) {
        int rl = idx >> 4, t = idx & 15;
        int row = r0 + rl;
        float v = accs[idx];
        if (res) v += res[(size_t)t * n_rows + row];
        out[(size_t)t * n_rows + row] = v;
    }
}

// ---------------- per-head rmsnorm + rope. grid (n_heads, T_NEW), 128 thr ----------------
__global__ void norm_rope_kernel(const float* __restrict__ in, const float* __restrict__ w,
                                 const float* __restrict__ cosb, const float* __restrict__ sinb,
                                 int n_heads, float* __restrict__ out_tl,
                                 float* __restrict__ out_ht, float* __restrict__ out_ht2) {
    int h = blockIdx.x, t = blockIdx.y;
    int d = threadIdx.x;
    float v = in[(size_t)t * n_heads * HD + h * HD + d];
    __shared__ float xs[HD];
    __shared__ float red[4];
    float p = v * v;
    #pragma unroll
    for (int o = 16; o; o >>= 1) p += __shfl_down_sync(0xffffffffu, p, o);
    if ((d & 31) == 0) red[d >> 5] = p;
    __syncthreads();
    float tot = red[0] + red[1] + red[2] + red[3];
    float r = rsqrtf(tot * (1.f / HD) + RMS_EPS);
    float xn = v * r * w[d];
    xs[d] = xn;
    __syncthreads();
    float other = (d < 64) ? -xs[d + 64] : xs[d - 64];
    float o = xn * cosb[t * HD + d] + other * sinb[t * HD + d];
    if (out_tl) out_tl[(size_t)t * n_heads * HD + h * HD + d] = o;
    size_t oht = ((size_t)h * T_NEW + t) * HD + d;
    if (out_ht) out_ht[oht] = o;
    if (out_ht2) out_ht2[oht] = o;
}

// ---------------- v copy [t][kvh*128+d] -> [kvh][t][d] x2 ----------------
__global__ void vcopy_kernel(const float* __restrict__ v, float* __restrict__ o1,
                             float* __restrict__ o2) {
    int i = blockIdx.x * 256 + threadIdx.x;
    if (i >= N_KV * T_NEW * HD) return;
    int d = i & 127;
    int t = (i >> 7) & 15;
    int h = i >> 11;
    float val = v[(size_t)t * N_KV * HD + h * HD + d];
    o1[i] = val;
    o2[i] = val;
}

// ---------------- scores: grid (32 chunks, 8 kvh), 128 thr, smem 128*129*4 ----------------
__global__ void scores_kernel(const float* __restrict__ cache_k, const float* __restrict__ knew,
                              const float* __restrict__ qb, float* __restrict__ scores) {
    extern __shared__ float ksh[];  // [128][129]
    int kvh = blockIdx.y, kbase = blockIdx.x * 128;
    for (int idx = threadIdx.x; idx < 128 * 128; idx += 128) {
        int kk = idx >> 7, c = idx & 127;
        int key = kbase + kk;
        float v = (key < T_CACHE)
                      ? cache_k[((size_t)kvh * T_CACHE + key) * HD + c]
                      : knew[((size_t)kvh * T_NEW + (key - T_CACHE)) * HD + c];
        ksh[kk * 129 + c] = v;
    }
    __syncthreads();
    int k = threadIdx.x;
    const float scale = 0.08838834764831845f;
    for (int qh = 0; qh < 4; qh++) {
        int h = kvh * 4 + qh;
        float acc[16];
        #pragma unroll
        for (int t = 0; t < 16; t++) acc[t] = 0.f;
        for (int c = 0; c < HD; c++) {
            float kv = ksh[k * 129 + c];
            #pragma unroll
            for (int t = 0; t < 16; t++)
                acc[t] += kv * qb[(size_t)t * N_HEADS * HD + h * HD + c];
        }
        #pragma unroll
        for (int t = 0; t < 16; t++)
            scores[((size_t)h * T_NEW + t) * SEQ + kbase + k] = acc[t] * scale;
    }
}

// ---------------- softmax: grid 512 (h*16+t), 256 thr ----------------
__global__ void softmax_kernel(float* __restrict__ scores) {
    int row = blockIdx.x;
    int t = row & 15;
    int L = T_CACHE + t + 1;
    float* s = scores + (size_t)row * SEQ;
    float v[16];
    float m = -1e30f;
    #pragma unroll
    for (int j = 0; j < 16; j++) {
        int i = threadIdx.x + j * 256;
        float x = (i < L) ? s[i] : -1e30f;
        v[j] = x;
        m = fmaxf(m, x);
    }
    __shared__ float sred[8];
    __shared__ float sb;
    int lane = threadIdx.x & 31, wid = threadIdx.x >> 5;
    #pragma unroll
    for (int o = 16; o; o >>= 1) m = fmaxf(m, __shfl_down_sync(0xffffffffu, m, o));
    if (lane == 0) sred[wid] = m;
    __syncthreads();
    if (threadIdx.x == 0) {
        float mm = sred[0];
        for (int i = 1; i < 8; i++) mm = fmaxf(mm, sred[i]);
        sb = mm;
    }
    __syncthreads();
    m = sb;
    float sum = 0.f;
    #pragma unroll
    for (int j = 0; j < 16; j++) {
        float e = (v[j] > -1e29f) ? __expf(v[j] - m) : 0.f;
        v[j] = e;
        sum += e;
    }
    __syncthreads();
    #pragma unroll
    for (int o = 16; o; o >>= 1) sum += __shfl_down_sync(0xffffffffu, sum, o);
    if (lane == 0) sred[wid] = sum;
    __syncthreads();
    if (threadIdx.x == 0) {
        float ss = 0.f;
        for (int i = 0; i < 8; i++) ss += sred[i];
        sb = 1.f / ss;
    }
    __syncthreads();
    float inv = sb;
    #pragma unroll
    for (int j = 0; j < 16; j++) s[threadIdx.x + j * 256] = v[j] * inv;
}

__global__ void zero_kernel(float* __restrict__ p, int n) {
    int i = blockIdx.x * 256 + threadIdx.x;
    if (i < n) p[i] = 0.f;
}

// ---------------- attn@V: grid (32 chunks, 8 kvh), 128 thr, smem 128*128*4 ----------------
__global__ void attnv_kernel(const float* __restrict__ cache_v, const float* __restrict__ vnew,
                             const float* __restrict__ attn, float* __restrict__ out) {
    extern __shared__ float vsh[];  // [128][128], threads index d -> conflict free
    int kvh = blockIdx.y, kbase = blockIdx.x * 128;
    for (int idx = threadIdx.x; idx < 128 * 128; idx += 128) {
        int kk = idx >> 7, c = idx & 127;
        int key = kbase + kk;
        float v = (key < T_CACHE)
                      ? cache_v[((size_t)kvh * T_CACHE + key) * HD + c]
                      : vnew[((size_t)kvh * T_NEW + (key - T_CACHE)) * HD + c];
        vsh[kk * 128 + c] = v;
    }
    __syncthreads();
    int d = threadIdx.x;
    for (int qh = 0; qh < 4; qh++) {
        int h = kvh * 4 + qh;
        for (int t0 = 0; t0 < 16; t0 += 4) {
            const float* a0 = attn + ((size_t)h * T_NEW + t0) * SEQ + kbase;
            float acc0 = 0.f, acc1 = 0.f, acc2 = 0.f, acc3 = 0.f;
            #pragma unroll 4
            for (int k = 0; k < 128; k++) {
                float vv = vsh[k * 128 + d];
                acc0 += a0[k] * vv;
                acc1 += a0[SEQ + k] * vv;
                acc2 += a0[2 * SEQ + k] * vv;
                acc3 += a0[3 * SEQ + k] * vv;
            }
            atomicAdd(&out[(size_t)(t0 + 0) * N_HEADS * HD + h * HD + d], acc0);
            atomicAdd(&out[(size_t)(t0 + 1) * N_HEADS * HD + h * HD + d], acc1);
            atomicAdd(&out[(size_t)(t0 + 2) * N_HEADS * HD + h * HD + d], acc2);
            atomicAdd(&out[(size_t)(t0 + 3) * N_HEADS * HD + h * HD + d], acc3);
        }
    }
}

// ---------------- silu(g)*u ----------------
__global__ void act_kernel(const float* __restrict__ g, const float* __restrict__ u,
                           float* __restrict__ a, int n) {
    int i = blockIdx.x * 256 + threadIdx.x;
    if (i < n) {
        float x = g[i];
        float s = x / (1.f + __expf(-x));
        a[i] = s * u[i];
    }
}

// ---------------- launch ----------------
extern "C" void kernel_launch(void* const* d_in, const int* in_sizes, int n_in,
                              void* d_out, int out_size) {
    const float* x        = (const float*)d_in[0];
    const float* cos_q    = (const float*)d_in[1];
    const float* sin_q    = (const float*)d_in[2];
    const float* cos_k    = (const float*)d_in[3];
    const float* sin_k    = (const float*)d_in[4];
    const float* cache_k  = (const float*)d_in[5];
    const float* cache_v  = (const float*)d_in[6];
    // d_in[7] = causal_mask (handled analytically)
    const float* in_ln_w  = (const float*)d_in[8];
    const float* post_ln_w= (const float*)d_in[9];
    const float* q_norm_w = (const float*)d_in[10];
    const float* k_norm_w = (const float*)d_in[11];
    const float* q_w      = (const float*)d_in[12];
    const float* k_w      = (const float*)d_in[13];
    const float* v_w      = (const float*)d_in[14];
    const float* o_w      = (const float*)d_in[15];
    const float* gate_w   = (const float*)d_in[16];
    const float* up_w     = (const float*)d_in[17];
    const float* down_w   = (const float*)d_in[18];

    float* out_final = (float*)d_out;                       // [16][2560]
    float* out_newk  = (float*)d_out + T_NEW * HIDDEN;      // [8][16][128]
    float* out_newv  = out_newk + N_KV * T_NEW * HD;        // [8][16][128]

    float *y, *q, *k, *v, *knew, *vnew, *scores, *attn, *h, *y2, *gg, *uu, *aa;
    cudaGetSymbolAddress((void**)&y, g_y);
    cudaGetSymbolAddress((void**)&q, g_q);
    cudaGetSymbolAddress((void**)&k, g_k);
    cudaGetSymbolAddress((void**)&v, g_v);
    cudaGetSymbolAddress((void**)&knew, g_knew);
    cudaGetSymbolAddress((void**)&vnew, g_vnew);
    cudaGetSymbolAddress((void**)&scores, g_scores);
    cudaGetSymbolAddress((void**)&attn, g_attn);
    cudaGetSymbolAddress((void**)&h, g_h);
    cudaGetSymbolAddress((void**)&y2, g_y2);
    cudaGetSymbolAddress((void**)&gg, g_gate);
    cudaGetSymbolAddress((void**)&uu, g_up);
    cudaGetSymbolAddress((void**)&aa, g_act);

    cudaFuncSetAttribute(gemm16_kernel, cudaFuncAttributeMaxDynamicSharedMemorySize, 16 * 1280 * 4 + 2048);
    cudaFuncSetAttribute(scores_kernel, cudaFuncAttributeMaxDynamicSharedMemorySize, 128 * 129 * 4);
    cudaFuncSetAttribute(attnv_kernel, cudaFuncAttributeMaxDynamicSharedMemorySize, 128 * 128 * 4);

    // 1. input rmsnorm
    rmsnorm_kernel<<<T_NEW, 256>>>(x, in_ln_w, y, HIDDEN);

    // 2-4. qkv projections
    {
        int KC = 1280;
        size_t smem_q = 16 * KC * 4 + 16 * 16 * 4;
        gemm16_kernel<<<4096 / 16, 256, smem_q>>>(q_w, y, q, nullptr, HIDDEN, KC, 4096, 2);
        size_t smem_kv = 16 * KC * 4 + 8 * 16 * 4;
        gemm16_kernel<<<1024 / 8, 256, smem_kv>>>(k_w, y, k, nullptr, HIDDEN, KC, 1024, 1);
        gemm16_kernel<<<1024 / 8, 256, smem_kv>>>(v_w, y, v, nullptr, HIDDEN, KC, 1024, 1);
    }

    // 5-7. q/k norm+rope, v copy (also into d_out)
    norm_rope_kernel<<<dim3(N_HEADS, T_NEW), HD>>>(q, q_norm_w, cos_q, sin_q, N_HEADS, q, nullptr, nullptr);
    norm_rope_kernel<<<dim3(N_KV, T_NEW), HD>>>(k, k_norm_w, cos_k, sin_k, N_KV, nullptr, knew, out_newk);
    vcopy_kernel<<<(N_KV * T_NEW * HD + 255) / 256, 256>>>(v, vnew, out_newv);

    // 8-11. attention
    zero_kernel<<<(T_NEW * N_HEADS * HD + 255) / 256, 256>>>(attn, T_NEW * N_HEADS * HD);
    scores_kernel<<<dim3(32, 8), 128, 128 * 129 * 4>>>(cache_k, knew, q, scores);
    softmax_kernel<<<N_HEADS * T_NEW, 256>>>(scores);
    attnv_kernel<<<dim3(32, 8), 128, 128 * 128 * 4>>>(cache_v, vnew, scores, attn);

    // 12. o projection + residual
    {
        int KC = 1024;
        size_t smem = 16 * KC * 4 + 8 * 16 * 4;
        gemm16_kernel<<<HIDDEN / 8, 256, smem>>>(o_w, attn, h, x, 4096, KC, HIDDEN, 1);
    }

    // 13. post rmsnorm
    rmsnorm_kernel<<<T_NEW, 256>>>(h, post_ln_w, y2, HIDDEN);

    // 14-16. gate/up + activation
    {
        int KC = 1280;
        size_t smem = 16 * KC * 4 + 32 * 16 * 4;
        gemm16_kernel<<<INTER / 32, 256, smem>>>(gate_w, y2, gg, nullptr, HIDDEN, KC, INTER, 4);
        gemm16_kernel<<<INTER / 32, 256, smem>>>(up_w, y2, uu, nullptr, HIDDEN, KC, INTER, 4);
    }
    act_kernel<<<(T_NEW * INTER + 255) / 256, 256>>>(gg, uu, aa, T_NEW * INTER);

    // 17. down projection + residual -> final output
    {
        int KC = 1216;
        size_t smem = 16 * KC * 4 + 8 * 16 * 4;
        gemm16_kernel<<<HIDDEN / 8, 256, smem>>>(down_w, aa, out_final, h, INTER, KC, HIDDEN, 1);
    }
    (void)in_sizes; (void)n_in; (void)out_size;
}

// round 2
// speedup vs baseline: 1.3698x; 1.3698x over previous
#include <cuda_runtime.h>
#include <cuda_bf16.h>
#include <math.h>

#define T_NEW 16
#define HIDDEN 2560
#define INTER 9728
#define N_HEADS 32
#define N_KV 8
#define HD 128
#define T_CACHE 4080
#define SEQ 4096
#define RMS_EPS 1e-6f

// ---- packed f32x2 helpers ----
#define FMA_F32X2(d, a, b) \
    asm("fma.rn.f32x2 %0, %1, %2, %0;" : "+l"(d) : "l"(a), "l"(b))
#define ADD_F32X2(d, a, b) \
    asm("add.rn.f32x2 %0, %1, %2;" : "=l"(d) : "l"(a), "l"(b))
#define PACKDUP(d, f) \
    do { unsigned int _u = __float_as_uint(f); \
         asm("mov.b64 %0, {%1, %1};" : "=l"(d) : "r"(_u)); } while (0)

// ---------------- scratch ----------------
__device__ float g_y[T_NEW * HIDDEN];
__device__ float g_q[T_NEW * N_HEADS * HD];
__device__ float g_k[T_NEW * N_KV * HD];
__device__ float g_v[T_NEW * N_KV * HD];
__device__ float g_knew[N_KV * T_NEW * HD];
__device__ float g_vnew[N_KV * T_NEW * HD];
__device__ float g_scores[N_HEADS * T_NEW * SEQ];
__device__ float g_attn[T_NEW * N_HEADS * HD];
__device__ float g_h[T_NEW * HIDDEN];
__device__ float g_y2[T_NEW * HIDDEN];
__device__ float g_gate[T_NEW * INTER];
__device__ float g_up[T_NEW * INTER];
__device__ float g_act[T_NEW * INTER];

// ---------------- rmsnorm (K=2560), grid = T_NEW, 256 thr ----------------
__global__ void rmsnorm_kernel(const float* __restrict__ x, const float* __restrict__ w,
                               float* __restrict__ y, int K) {
    int t = blockIdx.x;
    const float* xr = x + (size_t)t * K;
    float vals[10];
    float ss = 0.f;
    int n = 0;
    for (int i = threadIdx.x; i < K; i += 256, n++) {
        float v = xr[i];
        vals[n] = v;
        ss += v * v;
    }
    __shared__ float sred[8];
    __shared__ float stot;
    #pragma unroll
    for (int o = 16; o; o >>= 1) ss += __shfl_down_sync(0xffffffffu, ss, o);
    int lane = threadIdx.x & 31, wid = threadIdx.x >> 5;
    if (lane == 0) sred[wid] = ss;
    __syncthreads();
    if (threadIdx.x == 0) {
        float tot = 0.f;
        for (int i = 0; i < 8; i++) tot += sred[i];
        stot = tot;
    }
    __syncthreads();
    float r = rsqrtf(stot / (float)K + RMS_EPS);
    n = 0;
    for (int i = threadIdx.x; i < K; i += 256, n++)
        y[(size_t)t * K + i] = vals[n] * r * w[i];
}

// ---------------- GEMV (16 tokens) with f32x2 packed math ----------------
// 256 threads (8 warps), each warp handles RPW=4 rows. Y chunk staged in SMEM
// transposed with pitch 20 floats: ysh[c*20 + t] = Y[t][c0+c].
// Up to 3 row-segments (merged launches). Multi-chunk => atomicAdd outputs.
template <bool ATOMIC>
__global__ void gemv_f32x2(const float* __restrict__ W0, const float* __restrict__ W1,
                           const float* __restrict__ W2,
                           float* __restrict__ O0, float* __restrict__ O1,
                           float* __restrict__ O2,
                           int rows0, int rows1,
                           int cols0, int cols1, int cols2,
                           const float* __restrict__ Y, int K, int KC, int n_rowblocks) {
    extern __shared__ float ysh[];
    const int PITCH = 20;
    const int RPW = 4;
    int rb = blockIdx.x % n_rowblocks;
    int chunk = blockIdx.x / n_rowblocks;
    int c0 = chunk * KC;
    int tid = threadIdx.x, lane = tid & 31, wid = tid >> 5;
    int r0 = rb * 32;  // 8 warps * 4 rows

    const float* W;
    float* O;
    int colbase, ncols;
    if (r0 < rows0) {
        W = W0 + (size_t)r0 * K; O = O0; colbase = r0; ncols = cols0;
    } else if (r0 < rows0 + rows1) {
        W = W1 + (size_t)(r0 - rows0) * K; O = O1; colbase = r0 - rows0; ncols = cols1;
    } else {
        W = W2 + (size_t)(r0 - rows0 - rows1) * K; O = O2;
        colbase = r0 - rows0 - rows1; ncols = cols2;
    }

    // stage Y chunk transposed
    int KC4 = KC >> 2;
    for (int idx = tid; idx < 16 * KC4; idx += 256) {
        int t = idx / KC4, i = idx - t * KC4;
        float4 v = *reinterpret_cast<const float4*>(Y + (size_t)t * K + c0 + i * 4);
        int c = i * 4;
        ysh[(c + 0) * PITCH + t] = v.x;
        ysh[(c + 1) * PITCH + t] = v.y;
        ysh[(c + 2) * PITCH + t] = v.z;
        ysh[(c + 3) * PITCH + t] = v.w;
    }
    __syncthreads();

    const float4* wp[RPW];
    #pragma unroll
    for (int rr = 0; rr < RPW; rr++)
        wp[rr] = reinterpret_cast<const float4*>(W + (size_t)(wid * RPW + rr) * K + c0);

    unsigned long long acc[RPW][8];
    #pragma unroll
    for (int rr = 0; rr < RPW; rr++)
        #pragma unroll
        for (int p = 0; p < 8; p++) acc[rr][p] = 0ull;

    int nIter = KC4 >> 5;  // KC4 / 32
    float4 wc[RPW];
    #pragma unroll
    for (int rr = 0; rr < RPW; rr++) wc[rr] = wp[rr][lane];

    for (int j = 0; j < nIter; j++) {
        float4 wn[RPW];
        if (j + 1 < nIter) {
            #pragma unroll
            for (int rr = 0; rr < RPW; rr++) wn[rr] = wp[rr][(j + 1) * 32 + lane];
        }
        int cbase = (j * 32 + lane) * 4;
        #pragma unroll
        for (int cc = 0; cc < 4; cc++) {
            int c = cbase + cc;
            const ulonglong2* yq = reinterpret_cast<const ulonglong2*>(ysh + c * PITCH);
            unsigned long long wd[RPW];
            #pragma unroll
            for (int rr = 0; rr < RPW; rr++) {
                float ws = (cc == 0) ? wc[rr].x : (cc == 1) ? wc[rr].y
                         : (cc == 2) ? wc[rr].z : wc[rr].w;
                PACKDUP(wd[rr], ws);
            }
            #pragma unroll
            for (int q = 0; q < 4; q++) {
                ulonglong2 yv = yq[q];
                #pragma unroll
                for (int rr = 0; rr < RPW; rr++) {
                    FMA_F32X2(acc[rr][2 * q], wd[rr], yv.x);
                    FMA_F32X2(acc[rr][2 * q + 1], wd[rr], yv.y);
                }
            }
        }
        if (j + 1 < nIter) {
            #pragma unroll
            for (int rr = 0; rr < RPW; rr++) wc[rr] = wn[rr];
        }
    }

    // reduce + store
    #pragma unroll
    for (int rr = 0; rr < RPW; rr++) {
        #pragma unroll
        for (int p = 0; p < 8; p++) {
            unsigned long long v = acc[rr][p];
            #pragma unroll
            for (int o = 16; o; o >>= 1) {
                unsigned long long ov = __shfl_down_sync(0xffffffffu, v, o);
                ADD_F32X2(v, v, ov);
            }
            acc[rr][p] = v;
        }
        if (lane == 0) {
            int row = colbase + wid * RPW + rr;
            #pragma unroll
            for (int p = 0; p < 8; p++) {
                float lo = __uint_as_float((unsigned int)acc[rr][p]);
                float hi = __uint_as_float((unsigned int)(acc[rr][p] >> 32));
                if (ATOMIC) {
                    atomicAdd(&O[(size_t)(2 * p) * ncols + row], lo);
                    atomicAdd(&O[(size_t)(2 * p + 1) * ncols + row], hi);
                } else {
                    O[(size_t)(2 * p) * ncols + row] = lo;
                    O[(size_t)(2 * p + 1) * ncols + row] = hi;
                }
            }
        }
    }
}

// ---------------- per-head rmsnorm + rope. grid (n_heads, T_NEW), 128 thr ----------------
__global__ void norm_rope_kernel(const float* __restrict__ in, const float* __restrict__ w,
                                 const float* __restrict__ cosb, const float* __restrict__ sinb,
                                 int n_heads, float* __restrict__ out_tl,
                                 float* __restrict__ out_ht, float* __restrict__ out_ht2) {
    int h = blockIdx.x, t = blockIdx.y;
    int d = threadIdx.x;
    float v = in[(size_t)t * n_heads * HD + h * HD + d];
    __shared__ float xs[HD];
    __shared__ float red[4];
    float p = v * v;
    #pragma unroll
    for (int o = 16; o; o >>= 1) p += __shfl_down_sync(0xffffffffu, p, o);
    if ((d & 31) == 0) red[d >> 5] = p;
    __syncthreads();
    float tot = red[0] + red[1] + red[2] + red[3];
    float r = rsqrtf(tot * (1.f / HD) + RMS_EPS);
    float xn = v * r * w[d];
    xs[d] = xn;
    __syncthreads();
    float other = (d < 64) ? -xs[d + 64] : xs[d - 64];
    float o = xn * cosb[t * HD + d] + other * sinb[t * HD + d];
    if (out_tl) out_tl[(size_t)t * n_heads * HD + h * HD + d] = o;
    size_t oht = ((size_t)h * T_NEW + t) * HD + d;
    if (out_ht) out_ht[oht] = o;
    if (out_ht2) out_ht2[oht] = o;
}

// ---------------- v copy [t][kvh*128+d] -> [kvh][t][d] x2 ----------------
__global__ void vcopy_kernel(const float* __restrict__ v, float* __restrict__ o1,
                             float* __restrict__ o2) {
    int i = blockIdx.x * 256 + threadIdx.x;
    if (i >= N_KV * T_NEW * HD) return;
    int d = i & 127;
    int t = (i >> 7) & 15;
    int h = i >> 11;
    float val = v[(size_t)t * N_KV * HD + h * HD + d];
    o1[i] = val;
    o2[i] = val;
}

__global__ void copy_kernel(const float* __restrict__ s, float* __restrict__ d, int n) {
    int i = blockIdx.x * 256 + threadIdx.x;
    if (i < n) d[i] = s[i];
}

__global__ void zero_kernel(float* __restrict__ p, int n) {
    int i = blockIdx.x * 256 + threadIdx.x;
    if (i < n) p[i] = 0.f;
}

// ---------------- scores: grid (32 chunks, 8 kvh), 128 thr ----------------
// smem: ksh[128][129] + qsh[4][128*16] (q transposed [c][t], scale folded in)
__global__ void scores_kernel(const float* __restrict__ cache_k, const float* __restrict__ knew,
                              const float* __restrict__ qb, float* __restrict__ scores) {
    extern __shared__ float sm[];
    float* ksh = sm;                // 128*129
    float* qsh = sm + 128 * 129;    // 4 * 2048
    int kvh = blockIdx.y, kbase = blockIdx.x * 128;
    int tid = threadIdx.x;
    const float scale = 0.08838834764831845f;
    for (int idx = tid; idx < 128 * 128; idx += 128) {
        int kk = idx >> 7, c = idx & 127;
        int key = kbase + kk;
        float v = (key < T_CACHE)
                      ? cache_k[((size_t)kvh * T_CACHE + key) * HD + c]
                      : knew[((size_t)kvh * T_NEW + (key - T_CACHE)) * HD + c];
        ksh[kk * 129 + c] = v;
    }
    // stage q (4 heads), transposed, scaled
    for (int idx = tid; idx < 4 * 16 * 32; idx += 128) {
        int hh = idx >> 9;
        int rem = idx & 511;
        int t = rem >> 5;
        int c = (rem & 31) * 4;
        float4 v = *reinterpret_cast<const float4*>(
            qb + (size_t)t * (N_HEADS * HD) + (kvh * 4 + hh) * HD + c);
        float* qd = qsh + hh * 2048;
        qd[(c + 0) * 16 + t] = v.x * scale;
        qd[(c + 1) * 16 + t] = v.y * scale;
        qd[(c + 2) * 16 + t] = v.z * scale;
        qd[(c + 3) * 16 + t] = v.w * scale;
    }
    __syncthreads();

    int k = tid;
    #pragma unroll
    for (int hh = 0; hh < 4; hh++) {
        int h = kvh * 4 + hh;
        const float* qd = qsh + hh * 2048;
        unsigned long long acc[8];
        #pragma unroll
        for (int p = 0; p < 8; p++) acc[p] = 0ull;
        for (int c = 0; c < HD; c++) {
            float kv = ksh[k * 129 + c];
            unsigned long long kd;
            PACKDUP(kd, kv);
            const ulonglong2* qq = reinterpret_cast<const ulonglong2*>(qd + c * 16);
            #pragma unroll
            for (int q = 0; q < 4; q++) {
                ulonglong2 pv = qq[q];
                FMA_F32X2(acc[2 * q], kd, pv.x);
                FMA_F32X2(acc[2 * q + 1], kd, pv.y);
            }
        }
        #pragma unroll
        for (int p = 0; p < 8; p++) {
            float lo = __uint_as_float((unsigned int)acc[p]);
            float hi = __uint_as_float((unsigned int)(acc[p] >> 32));
            scores[((size_t)h * T_NEW + 2 * p) * SEQ + kbase + k] = lo;
            scores[((size_t)h * T_NEW + 2 * p + 1) * SEQ + kbase + k] = hi;
        }
    }
}

// ---------------- softmax: grid 512 (h*16+t), 256 thr ----------------
__global__ void softmax_kernel(float* __restrict__ scores) {
    int row = blockIdx.x;
    int t = row & 15;
    int L = T_CACHE + t + 1;
    float* s = scores + (size_t)row * SEQ;
    float v[16];
    float m = -1e30f;
    #pragma unroll
    for (int j = 0; j < 16; j++) {
        int i = threadIdx.x + j * 256;
        float x = (i < L) ? s[i] : -1e30f;
        v[j] = x;
        m = fmaxf(m, x);
    }
    __shared__ float sred[8];
    __shared__ float sb;
    int lane = threadIdx.x & 31, wid = threadIdx.x >> 5;
    #pragma unroll
    for (int o = 16; o; o >>= 1) m = fmaxf(m, __shfl_down_sync(0xffffffffu, m, o));
    if (lane == 0) sred[wid] = m;
    __syncthreads();
    if (threadIdx.x == 0) {
        float mm = sred[0];
        for (int i = 1; i < 8; i++) mm = fmaxf(mm, sred[i]);
        sb = mm;
    }
    __syncthreads();
    m = sb;
    float sum = 0.f;
    #pragma unroll
    for (int j = 0; j < 16; j++) {
        float e = (v[j] > -1e29f) ? __expf(v[j] - m) : 0.f;
        v[j] = e;
        sum += e;
    }
    __syncthreads();
    #pragma unroll
    for (int o = 16; o; o >>= 1) sum += __shfl_down_sync(0xffffffffu, sum, o);
    if (lane == 0) sred[wid] = sum;
    __syncthreads();
    if (threadIdx.x == 0) {
        float ss = 0.f;
        for (int i = 0; i < 8; i++) ss += sred[i];
        sb = 1.f / ss;
    }
    __syncthreads();
    float inv = sb;
    #pragma unroll
    for (int j = 0; j < 16; j++) s[threadIdx.x + j * 256] = v[j] * inv;
}

// ---------------- attn@V: grid (32 chunks, 8 kvh), 128 thr ----------------
// smem: vsh[128][128] + ash[128*16] (attn transposed per head)
__global__ void attnv_kernel(const float* __restrict__ cache_v, const float* __restrict__ vnew,
                             const float* __restrict__ attn, float* __restrict__ out) {
    extern __shared__ float sm[];
    float* vsh = sm;            // 128*128
    float* ash = sm + 128 * 128;  // 128*16
    int kvh = blockIdx.y, kbase = blockIdx.x * 128;
    int tid = threadIdx.x;
    for (int idx = tid; idx < 128 * 128; idx += 128) {
        int kk = idx >> 7, c = idx & 127;
        int key = kbase + kk;
        float v = (key < T_CACHE)
                      ? cache_v[((size_t)kvh * T_CACHE + key) * HD + c]
                      : vnew[((size_t)kvh * T_NEW + (key - T_CACHE)) * HD + c];
        vsh[kk * 128 + c] = v;
    }
    __syncthreads();
    int d = tid;
    for (int hh = 0; hh < 4; hh++) {
        int h = kvh * 4 + hh;
        for (int idx = tid; idx < 16 * 128; idx += 128) {
            int t = idx >> 7, k = idx & 127;
            ash[k * 16 + t] = attn[((size_t)h * T_NEW + t) * SEQ + kbase + k];
        }
        __syncthreads();
        unsigned long long acc[8];
        #pragma unroll
        for (int p = 0; p < 8; p++) acc[p] = 0ull;
        for (int k = 0; k < 128; k++) {
            float vv = vsh[k * 128 + d];
            unsigned long long vd;
            PACKDUP(vd, vv);
            const ulonglong2* ap = reinterpret_cast<const ulonglong2*>(ash + k * 16);
            #pragma unroll
            for (int q = 0; q < 4; q++) {
                ulonglong2 pv = ap[q];
                FMA_F32X2(acc[2 * q], vd, pv.x);
                FMA_F32X2(acc[2 * q + 1], vd, pv.y);
            }
        }
        #pragma unroll
        for (int p = 0; p < 8; p++) {
            float lo = __uint_as_float((unsigned int)acc[p]);
            float hi = __uint_as_float((unsigned int)(acc[p] >> 32));
            atomicAdd(&out[(size_t)(2 * p) * N_HEADS * HD + h * HD + d], lo);
            atomicAdd(&out[(size_t)(2 * p + 1) * N_HEADS * HD + h * HD + d], hi);
        }
        __syncthreads();
    }
}

// ---------------- silu(g)*u ----------------
__global__ void act_kernel(const float* __restrict__ g, const float* __restrict__ u,
                           float* __restrict__ a, int n) {
    int i = blockIdx.x * 256 + threadIdx.x;
    if (i < n) {
        float x = g[i];
        float s = x / (1.f + __expf(-x));
        a[i] = s * u[i];
    }
}

// ---------------- launch ----------------
extern "C" void kernel_launch(void* const* d_in, const int* in_sizes, int n_in,
                              void* d_out, int out_size) {
    const float* x         = (const float*)d_in[0];
    const float* cos_q     = (const float*)d_in[1];
    const float* sin_q     = (const float*)d_in[2];
    const float* cos_k     = (const float*)d_in[3];
    const float* sin_k     = (const float*)d_in[4];
    const float* cache_k   = (const float*)d_in[5];
    const float* cache_v   = (const float*)d_in[6];
    const float* in_ln_w   = (const float*)d_in[8];
    const float* post_ln_w = (const float*)d_in[9];
    const float* q_norm_w  = (const float*)d_in[10];
    const float* k_norm_w  = (const float*)d_in[11];
    const float* q_w       = (const float*)d_in[12];
    const float* k_w       = (const float*)d_in[13];
    const float* v_w       = (const float*)d_in[14];
    const float* o_w       = (const float*)d_in[15];
    const float* gate_w    = (const float*)d_in[16];
    const float* up_w      = (const float*)d_in[17];
    const float* down_w    = (const float*)d_in[18];

    float* out_final = (float*)d_out;
    float* out_newk  = (float*)d_out + T_NEW * HIDDEN;
    float* out_newv  = out_newk + N_KV * T_NEW * HD;

    float *y, *q, *k, *v, *knew, *vnew, *scores, *attn, *h, *y2, *gg, *uu, *aa;
    cudaGetSymbolAddress((void**)&y, g_y);
    cudaGetSymbolAddress((void**)&q, g_q);
    cudaGetSymbolAddress((void**)&k, g_k);
    cudaGetSymbolAddress((void**)&v, g_v);
    cudaGetSymbolAddress((void**)&knew, g_knew);
    cudaGetSymbolAddress((void**)&vnew, g_vnew);
    cudaGetSymbolAddress((void**)&scores, g_scores);
    cudaGetSymbolAddress((void**)&attn, g_attn);
    cudaGetSymbolAddress((void**)&h, g_h);
    cudaGetSymbolAddress((void**)&y2, g_y2);
    cudaGetSymbolAddress((void**)&gg, g_gate);
    cudaGetSymbolAddress((void**)&uu, g_up);
    cudaGetSymbolAddress((void**)&aa, g_act);

    cudaFuncSetAttribute(gemv_f32x2<false>, cudaFuncAttributeMaxDynamicSharedMemorySize, 2560 * 20 * 4);
    cudaFuncSetAttribute(gemv_f32x2<true>, cudaFuncAttributeMaxDynamicSharedMemorySize, 2432 * 20 * 4);
    cudaFuncSetAttribute(scores_kernel, cudaFuncAttributeMaxDynamicSharedMemorySize, 128 * 129 * 4 + 4 * 2048 * 4);
    cudaFuncSetAttribute(attnv_kernel, cudaFuncAttributeMaxDynamicSharedMemorySize, 128 * 128 * 4 + 128 * 16 * 4);

    // 1. input rmsnorm
    rmsnorm_kernel<<<T_NEW, 256>>>(x, in_ln_w, y, HIDDEN);

    // 2. merged qkv projection (rows: 4096 q | 1024 k | 1024 v)
    gemv_f32x2<false><<<192, 256, 2560 * 20 * 4>>>(
        q_w, k_w, v_w, q, k, v, 4096, 1024,
        N_HEADS * HD, N_KV * HD, N_KV * HD, y, HIDDEN, HIDDEN, 192);

    // 3-5. q/k norm+rope, v copy (k/v also into d_out)
    norm_rope_kernel<<<dim3(N_HEADS, T_NEW), HD>>>(q, q_norm_w, cos_q, sin_q, N_HEADS, q, nullptr, nullptr);
    norm_rope_kernel<<<dim3(N_KV, T_NEW), HD>>>(k, k_norm_w, cos_k, sin_k, N_KV, nullptr, knew, out_newk);
    vcopy_kernel<<<(N_KV * T_NEW * HD + 255) / 256, 256>>>(v, vnew, out_newv);

    // 6. residual pre-init h = x
    copy_kernel<<<(T_NEW * HIDDEN + 255) / 256, 256>>>(x, h, T_NEW * HIDDEN);

    // 7-10. attention
    zero_kernel<<<(T_NEW * N_HEADS * HD + 255) / 256, 256>>>(attn, T_NEW * N_HEADS * HD);
    scores_kernel<<<dim3(32, 8), 128, 128 * 129 * 4 + 4 * 2048 * 4>>>(cache_k, knew, q, scores);
    softmax_kernel<<<N_HEADS * T_NEW, 256>>>(scores);
    attnv_kernel<<<dim3(32, 8), 128, 128 * 128 * 4 + 128 * 16 * 4>>>(cache_v, vnew, scores, attn);

    // 11. o projection (split-K 2 chunks, atomic into h)
    gemv_f32x2<true><<<160, 256, 2048 * 20 * 4>>>(
        o_w, nullptr, nullptr, h, nullptr, nullptr, HIDDEN, 0,
        HIDDEN, 0, 0, attn, N_HEADS * HD, 2048, 80);

    // 12. post rmsnorm
    rmsnorm_kernel<<<T_NEW, 256>>>(h, post_ln_w, y2, HIDDEN);

    // 13. merged gate+up
    gemv_f32x2<false><<<608, 256, 2560 * 20 * 4>>>(
        gate_w, up_w, nullptr, gg, uu, nullptr, INTER, INTER,
        INTER, INTER, 0, y2, HIDDEN, HIDDEN, 608);

    // 14. activation
    act_kernel<<<(T_NEW * INTER + 255) / 256, 256>>>(gg, uu, aa, T_NEW * INTER);

    // 15. residual pre-init out = h
    copy_kernel<<<(T_NEW * HIDDEN + 255) / 256, 256>>>(h, out_final, T_NEW * HIDDEN);

    // 16. down projection (split-K 4 chunks, atomic into out)
    gemv_f32x2<true><<<320, 256, 2432 * 20 * 4>>>(
        down_w, nullptr, nullptr, out_final, nullptr, nullptr, HIDDEN, 0,
        HIDDEN, 0, 0, aa, INTER, 2432, 80);

    (void)in_sizes; (void)n_in; (void)out_size;
}

// round 5
// speedup vs baseline: 2.0330x; 1.4841x over previous
#include <cuda_runtime.h>
#include <cuda_bf16.h>
#include <math.h>

#define T_NEW 16
#define HIDDEN 2560
#define INTER 9728
#define N_HEADS 32
#define N_KV 8
#define HD 128
#define T_CACHE 4080
#define SEQ 4096
#define RMS_EPS 1e-6f

// ---- packed f32x2 helpers ----
#define FMA_F32X2(d, a, b) \
    asm("fma.rn.f32x2 %0, %1, %2, %0;" : "+l"(d) : "l"(a), "l"(b))
#define ADD_F32X2(d, a, b) \
    asm("add.rn.f32x2 %0, %1, %2;" : "=l"(d) : "l"(a), "l"(b))
#define PACK2(d, lo, hi) \
    asm("mov.b64 %0, {%1, %2};" : "=l"(d) : "f"(lo), "f"(hi))
#define UNPACK2(lo, hi, v) \
    asm("mov.b64 {%0, %1}, %2;" : "=f"(lo), "=f"(hi) : "l"(v))
#define PACKDUP(d, f) \
    do { unsigned int _u = __float_as_uint(f); \
         asm("mov.b64 %0, {%1, %1};" : "=l"(d) : "r"(_u)); } while (0)

typedef unsigned long long ull;

// ---------------- scratch ----------------
__device__ float g_y[T_NEW * HIDDEN];
__device__ float g_q[T_NEW * N_HEADS * HD];
__device__ float g_k[T_NEW * N_KV * HD];
__device__ float g_v[T_NEW * N_KV * HD];
__device__ float g_knew[N_KV * T_NEW * HD];
__device__ float g_vnew[N_KV * T_NEW * HD];
__device__ float g_scores[N_HEADS * T_NEW * SEQ];
__device__ float g_attn[T_NEW * N_HEADS * HD];
__device__ float g_h[T_NEW * HIDDEN];
__device__ float g_y2[T_NEW * HIDDEN];
__device__ float g_gate[T_NEW * INTER];
__device__ float g_up[T_NEW * INTER];
__device__ float g_act[T_NEW * INTER];

// ---------------- rmsnorm (grid = T_NEW, 256 thr) ----------------
__global__ void rmsnorm_kernel(const float* __restrict__ x, const float* __restrict__ w,
                               float* __restrict__ y, int K) {
    int t = blockIdx.x;
    const float* xr = x + (size_t)t * K;
    float vals[10];
    float ss = 0.f;
    int n = 0;
    for (int i = threadIdx.x; i < K; i += 256, n++) {
        float v = xr[i];
        vals[n] = v;
        ss += v * v;
    }
    __shared__ float sred[8];
    __shared__ float stot;
    #pragma unroll
    for (int o = 16; o; o >>= 1) ss += __shfl_down_sync(0xffffffffu, ss, o);
    int lane = threadIdx.x & 31, wid = threadIdx.x >> 5;
    if (lane == 0) sred[wid] = ss;
    __syncthreads();
    if (threadIdx.x == 0) {
        float tot = 0.f;
        for (int i = 0; i < 8; i++) tot += sred[i];
        stot = tot;
    }
    __syncthreads();
    float r = rsqrtf(stot / (float)K + RMS_EPS);
    n = 0;
    for (int i = threadIdx.x; i < K; i += 256, n++)
        y[(size_t)t * K + i] = vals[n] * r * w[i];
}

// ---------------- GEMV (16 tokens), f32x2 column-pair scheme ----------------
// 256 threads = 8 warps, each warp 4 rows (32 rows/rowblock).
// Y chunk staged in SMEM natural [t][c] layout, pitch KC+4 (16B-multiple).
// Lane L covers columns 4L.. within a 128-col j-slab: LDS.128 conflict-free,
// each y load feeds 4 rows (8 FFMA2). Grid-stride over rowblocks; grid.y = K chunk.
template <bool ATOMIC>
__global__ void __launch_bounds__(256, 1)
gemv3(const float* __restrict__ W0, const float* __restrict__ W1,
      const float* __restrict__ W2,
      float* __restrict__ O0, float* __restrict__ O1, float* __restrict__ O2,
      int rows0, int rows1,
      int cols0, int cols1, int cols2,
      const float* __restrict__ Y, int K, int KC, int n_rowblocks) {
    extern __shared__ float ysh[];
    const int PITCH = KC + 4;
    int tid = threadIdx.x, lane = tid & 31, wid = tid >> 5;
    int c0 = blockIdx.y * KC;
    int KC4 = KC >> 2;

    // stage Y chunk [16][KC]
    for (int idx = tid; idx < 16 * KC4; idx += 256) {
        int t = idx / KC4, i = idx - t * KC4;
        float4 v = *reinterpret_cast<const float4*>(Y + (size_t)t * K + c0 + i * 4);
        *reinterpret_cast<float4*>(ysh + t * PITCH + i * 4) = v;
    }
    __syncthreads();

    int nIter = KC4 >> 5;  // KC / 128

    for (int rb = blockIdx.x; rb < n_rowblocks; rb += gridDim.x) {
        int r0 = rb * 32;
        const float* W;
        float* O;
        int colbase, ncols;
        if (r0 < rows0) {
            W = W0 + (size_t)r0 * K; O = O0; colbase = r0; ncols = cols0;
        } else if (r0 < rows0 + rows1) {
            W = W1 + (size_t)(r0 - rows0) * K; O = O1;
            colbase = r0 - rows0; ncols = cols1;
        } else {
            W = W2 + (size_t)(r0 - rows0 - rows1) * K; O = O2;
            colbase = r0 - rows0 - rows1; ncols = cols2;
        }
        const float* Wr = W + (size_t)wid * 4 * K + c0;
        #define WLD(rr, j) (reinterpret_cast<const float4*>(Wr + (size_t)(rr) * K)[(j) * 32 + lane])

        ull acc[4][16];
        #pragma unroll
        for (int rr = 0; rr < 4; rr++)
            #pragma unroll
            for (int t = 0; t < 16; t++) acc[rr][t] = 0ull;

        float4 wc[4], wn[4];
        #pragma unroll
        for (int rr = 0; rr < 4; rr++) wc[rr] = WLD(rr, 0);
        #pragma unroll
        for (int rr = 0; rr < 4; rr++) wn[rr] = WLD(rr, 1);

        for (int j = 0; j < nIter; j++) {
            float4 wf[4];
            #pragma unroll
            for (int rr = 0; rr < 4; rr++) wf[rr] = wn[rr];
            if (j + 2 < nIter) {
                #pragma unroll
                for (int rr = 0; rr < 4; rr++) wf[rr] = WLD(rr, j + 2);
            }
            ull a01[4], a23[4];
            #pragma unroll
            for (int rr = 0; rr < 4; rr++) {
                PACK2(a01[rr], wc[rr].x, wc[rr].y);
                PACK2(a23[rr], wc[rr].z, wc[rr].w);
            }
            const float* yb = ysh + ((j * 32 + lane) << 2);
            #pragma unroll
            for (int t = 0; t < 16; t++) {
                ulonglong2 yv = *reinterpret_cast<const ulonglong2*>(yb + t * PITCH);
                #pragma unroll
                for (int rr = 0; rr < 4; rr++) {
                    FMA_F32X2(acc[rr][t], a01[rr], yv.x);
                    FMA_F32X2(acc[rr][t], a23[rr], yv.y);
                }
            }
            #pragma unroll
            for (int rr = 0; rr < 4; rr++) { wc[rr] = wn[rr]; wn[rr] = wf[rr]; }
        }

        // reduce: fold even/odd columns, pack t-pairs, 64-bit shfl tree
        #pragma unroll
        for (int rr = 0; rr < 4; rr++) {
            int row = colbase + wid * 4 + rr;
            ull pk[8];
            #pragma unroll
            for (int p = 0; p < 8; p++) {
                float lo0, hi0, lo1, hi1;
                UNPACK2(lo0, hi0, acc[rr][2 * p]);
                UNPACK2(lo1, hi1, acc[rr][2 * p + 1]);
                float s0 = lo0 + hi0, s1 = lo1 + hi1;
                PACK2(pk[p], s0, s1);
            }
            #pragma unroll
            for (int p = 0; p < 8; p++) {
                ull v = pk[p];
                #pragma unroll
                for (int o = 16; o; o >>= 1) {
                    ull ov = __shfl_down_sync(0xffffffffu, v, o);
                    ADD_F32X2(v, v, ov);
                }
                if (lane == 0) {
                    float s0, s1;
                    UNPACK2(s0, s1, v);
                    if (ATOMIC) {
                        atomicAdd(&O[(size_t)(2 * p) * ncols + row], s0);
                        atomicAdd(&O[(size_t)(2 * p + 1) * ncols + row], s1);
                    } else {
                        O[(size_t)(2 * p) * ncols + row] = s0;
                        O[(size_t)(2 * p + 1) * ncols + row] = s1;
                    }
                }
            }
        }
        #undef WLD
    }
}

// ---------------- per-head rmsnorm + rope ----------------
__global__ void norm_rope_kernel(const float* __restrict__ in, const float* __restrict__ w,
                                 const float* __restrict__ cosb, const float* __restrict__ sinb,
                                 int n_heads, float* __restrict__ out_tl,
                                 float* __restrict__ out_ht, float* __restrict__ out_ht2) {
    int h = blockIdx.x, t = blockIdx.y;
    int d = threadIdx.x;
    float v = in[(size_t)t * n_heads * HD + h * HD + d];
    __shared__ float xs[HD];
    __shared__ float red[4];
    float p = v * v;
    #pragma unroll
    for (int o = 16; o; o >>= 1) p += __shfl_down_sync(0xffffffffu, p, o);
    if ((d & 31) == 0) red[d >> 5] = p;
    __syncthreads();
    float tot = red[0] + red[1] + red[2] + red[3];
    float r = rsqrtf(tot * (1.f / HD) + RMS_EPS);
    float xn = v * r * w[d];
    xs[d] = xn;
    __syncthreads();
    float other = (d < 64) ? -xs[d + 64] : xs[d - 64];
    float o = xn * cosb[t * HD + d] + other * sinb[t * HD + d];
    if (out_tl) out_tl[(size_t)t * n_heads * HD + h * HD + d] = o;
    size_t oht = ((size_t)h * T_NEW + t) * HD + d;
    if (out_ht) out_ht[oht] = o;
    if (out_ht2) out_ht2[oht] = o;
}

__global__ void vcopy_kernel(const float* __restrict__ v, float* __restrict__ o1,
                             float* __restrict__ o2) {
    int i = blockIdx.x * 256 + threadIdx.x;
    if (i >= N_KV * T_NEW * HD) return;
    int d = i & 127;
    int t = (i >> 7) & 15;
    int h = i >> 11;
    float val = v[(size_t)t * N_KV * HD + h * HD + d];
    o1[i] = val;
    o2[i] = val;
}

__global__ void copy_kernel(const float* __restrict__ s, float* __restrict__ d, int n) {
    int i = blockIdx.x * 256 + threadIdx.x;
    if (i < n) d[i] = s[i];
}

__global__ void zero_kernel(float* __restrict__ p, int n) {
    int i = blockIdx.x * 256 + threadIdx.x;
    if (i < n) p[i] = 0.f;
}

// ---------------- scores: grid (32 chunks, 8 kvh), 128 thr ----------------
__global__ void scores_kernel(const float* __restrict__ cache_k, const float* __restrict__ knew,
                              const float* __restrict__ qb, float* __restrict__ scores) {
    extern __shared__ float sm[];
    float* ksh = sm;              // 128*129
    float* qsh = sm + 128 * 129;  // 4 * 2048
    int kvh = blockIdx.y, kbase = blockIdx.x * 128;
    int tid = threadIdx.x;
    const float scale = 0.08838834764831845f;
    for (int idx = tid; idx < 128 * 128; idx += 128) {
        int kk = idx >> 7, c = idx & 127;
        int key = kbase + kk;
        float v = (key < T_CACHE)
                      ? cache_k[((size_t)kvh * T_CACHE + key) * HD + c]
                      : knew[((size_t)kvh * T_NEW + (key - T_CACHE)) * HD + c];
        ksh[kk * 129 + c] = v;
    }
    for (int idx = tid; idx < 4 * 16 * 32; idx += 128) {
        int hh = idx >> 9;
        int rem = idx & 511;
        int t = rem >> 5;
        int c = (rem & 31) * 4;
        float4 v = *reinterpret_cast<const float4*>(
            qb + (size_t)t * (N_HEADS * HD) + (kvh * 4 + hh) * HD + c);
        float* qd = qsh + hh * 2048;
        qd[(c + 0) * 16 + t] = v.x * scale;
        qd[(c + 1) * 16 + t] = v.y * scale;
        qd[(c + 2) * 16 + t] = v.z * scale;
        qd[(c + 3) * 16 + t] = v.w * scale;
    }
    __syncthreads();

    int k = tid;
    #pragma unroll
    for (int hh = 0; hh < 4; hh++) {
        int h = kvh * 4 + hh;
        const float* qd = qsh + hh * 2048;
        ull acc[8];
        #pragma unroll
        for (int p = 0; p < 8; p++) acc[p] = 0ull;
        for (int c = 0; c < HD; c++) {
            float kv = ksh[k * 129 + c];
            ull kd;
            PACKDUP(kd, kv);
            const ulonglong2* qq = reinterpret_cast<const ulonglong2*>(qd + c * 16);
            #pragma unroll
            for (int q = 0; q < 4; q++) {
                ulonglong2 pv = qq[q];
                FMA_F32X2(acc[2 * q], kd, pv.x);
                FMA_F32X2(acc[2 * q + 1], kd, pv.y);
            }
        }
        #pragma unroll
        for (int p = 0; p < 8; p++) {
            float lo, hi;
            UNPACK2(lo, hi, acc[p]);
            scores[((size_t)h * T_NEW + 2 * p) * SEQ + kbase + k] = lo;
            scores[((size_t)h * T_NEW + 2 * p + 1) * SEQ + kbase + k] = hi;
        }
    }
}

// ---------------- softmax: grid 512, 256 thr ----------------
__global__ void softmax_kernel(float* __restrict__ scores) {
    int row = blockIdx.x;
    int t = row & 15;
    int L = T_CACHE + t + 1;
    float* s = scores + (size_t)row * SEQ;
    float v[16];
    float m = -1e30f;
    #pragma unroll
    for (int j = 0; j < 16; j++) {
        int i = threadIdx.x + j * 256;
        float x = (i < L) ? s[i] : -1e30f;
        v[j] = x;
        m = fmaxf(m, x);
    }
    __shared__ float sred[8];
    __shared__ float sb;
    int lane = threadIdx.x & 31, wid = threadIdx.x >> 5;
    #pragma unroll
    for (int o = 16; o; o >>= 1) m = fmaxf(m, __shfl_down_sync(0xffffffffu, m, o));
    if (lane == 0) sred[wid] = m;
    __syncthreads();
    if (threadIdx.x == 0) {
        float mm = sred[0];
        for (int i = 1; i < 8; i++) mm = fmaxf(mm, sred[i]);
        sb = mm;
    }
    __syncthreads();
    m = sb;
    float sum = 0.f;
    #pragma unroll
    for (int j = 0; j < 16; j++) {
        float e = (v[j] > -1e29f) ? __expf(v[j] - m) : 0.f;
        v[j] = e;
        sum += e;
    }
    __syncthreads();
    #pragma unroll
    for (int o = 16; o; o >>= 1) sum += __shfl_down_sync(0xffffffffu, sum, o);
    if (lane == 0) sred[wid] = sum;
    __syncthreads();
    if (threadIdx.x == 0) {
        float ss = 0.f;
        for (int i = 0; i < 8; i++) ss += sred[i];
        sb = 1.f / ss;
    }
    __syncthreads();
    float inv = sb;
    #pragma unroll
    for (int j = 0; j < 16; j++) s[threadIdx.x + j * 256] = v[j] * inv;
}

// ---------------- attn@V: grid (32 chunks, 8 kvh), 128 thr ----------------
__global__ void attnv_kernel(const float* __restrict__ cache_v, const float* __restrict__ vnew,
                             const float* __restrict__ attn, float* __restrict__ out) {
    extern __shared__ float sm[];
    float* vsh = sm;               // 128*128
    float* ash = sm + 128 * 128;   // 128*16
    int kvh = blockIdx.y, kbase = blockIdx.x * 128;
    int tid = threadIdx.x;
    for (int idx = tid; idx < 128 * 128; idx += 128) {
        int kk = idx >> 7, c = idx & 127;
        int key = kbase + kk;
        float v = (key < T_CACHE)
                      ? cache_v[((size_t)kvh * T_CACHE + key) * HD + c]
                      : vnew[((size_t)kvh * T_NEW + (key - T_CACHE)) * HD + c];
        vsh[kk * 128 + c] = v;
    }
    __syncthreads();
    int d = tid;
    for (int hh = 0; hh < 4; hh++) {
        int h = kvh * 4 + hh;
        for (int idx = tid; idx < 16 * 128; idx += 128) {
            int t = idx >> 7, k = idx & 127;
            ash[k * 16 + t] = attn[((size_t)h * T_NEW + t) * SEQ + kbase + k];
        }
        __syncthreads();
        ull acc[8];
        #pragma unroll
        for (int p = 0; p < 8; p++) acc[p] = 0ull;
        for (int k = 0; k < 128; k++) {
            float vv = vsh[k * 128 + d];
            ull vd;
            PACKDUP(vd, vv);
            const ulonglong2* ap = reinterpret_cast<const ulonglong2*>(ash + k * 16);
            #pragma unroll
            for (int q = 0; q < 4; q++) {
                ulonglong2 pv = ap[q];
                FMA_F32X2(acc[2 * q], vd, pv.x);
                FMA_F32X2(acc[2 * q + 1], vd, pv.y);
            }
        }
        #pragma unroll
        for (int p = 0; p < 8; p++) {
            float lo, hi;
            UNPACK2(lo, hi, acc[p]);
            atomicAdd(&out[(size_t)(2 * p) * N_HEADS * HD + h * HD + d], lo);
            atomicAdd(&out[(size_t)(2 * p + 1) * N_HEADS * HD + h * HD + d], hi);
        }
        __syncthreads();
    }
}

// ---------------- silu(g)*u ----------------
__global__ void act_kernel(const float* __restrict__ g, const float* __restrict__ u,
                           float* __restrict__ a, int n) {
    int i = blockIdx.x * 256 + threadIdx.x;
    if (i < n) {
        float x = g[i];
        float s = x / (1.f + __expf(-x));
        a[i] = s * u[i];
    }
}

// ---------------- launch ----------------
extern "C" void kernel_launch(void* const* d_in, const int* in_sizes, int n_in,
                              void* d_out, int out_size) {
    const float* x         = (const float*)d_in[0];
    const float* cos_q     = (const float*)d_in[1];
    const float* sin_q     = (const float*)d_in[2];
    const float* cos_k     = (const float*)d_in[3];
    const float* sin_k     = (const float*)d_in[4];
    const float* cache_k   = (const float*)d_in[5];
    const float* cache_v   = (const float*)d_in[6];
    const float* in_ln_w   = (const float*)d_in[8];
    const float* post_ln_w = (const float*)d_in[9];
    const float* q_norm_w  = (const float*)d_in[10];
    const float* k_norm_w  = (const float*)d_in[11];
    const float* q_w       = (const float*)d_in[12];
    const float* k_w       = (const float*)d_in[13];
    const float* v_w       = (const float*)d_in[14];
    const float* o_w       = (const float*)d_in[15];
    const float* gate_w    = (const float*)d_in[16];
    const float* up_w      = (const float*)d_in[17];
    const float* down_w    = (const float*)d_in[18];

    float* out_final = (float*)d_out;
    float* out_newk  = (float*)d_out + T_NEW * HIDDEN;
    float* out_newv  = out_newk + N_KV * T_NEW * HD;

    float *y, *q, *k, *v, *knew, *vnew, *scores, *attn, *h, *y2, *gg, *uu, *aa;
    cudaGetSymbolAddress((void**)&y, g_y);
    cudaGetSymbolAddress((void**)&q, g_q);
    cudaGetSymbolAddress((void**)&k, g_k);
    cudaGetSymbolAddress((void**)&v, g_v);
    cudaGetSymbolAddress((void**)&knew, g_knew);
    cudaGetSymbolAddress((void**)&vnew, g_vnew);
    cudaGetSymbolAddress((void**)&scores, g_scores);
    cudaGetSymbolAddress((void**)&attn, g_attn);
    cudaGetSymbolAddress((void**)&h, g_h);
    cudaGetSymbolAddress((void**)&y2, g_y2);
    cudaGetSymbolAddress((void**)&gg, g_gate);
    cudaGetSymbolAddress((void**)&uu, g_up);
    cudaGetSymbolAddress((void**)&aa, g_act);

    // SMEM: 16 * (KC+4) * 4 bytes
    cudaFuncSetAttribute(gemv3<false>, cudaFuncAttributeMaxDynamicSharedMemorySize,
                         16 * (HIDDEN + 4) * 4);
    cudaFuncSetAttribute(gemv3<true>, cudaFuncAttributeMaxDynamicSharedMemorySize,
                         16 * (2432 + 4) * 4);
    cudaFuncSetAttribute(scores_kernel, cudaFuncAttributeMaxDynamicSharedMemorySize,
                         128 * 129 * 4 + 4 * 2048 * 4);
    cudaFuncSetAttribute(attnv_kernel, cudaFuncAttributeMaxDynamicSharedMemorySize,
                         128 * 128 * 4 + 128 * 16 * 4);

    // 1. input rmsnorm
    rmsnorm_kernel<<<T_NEW, 256>>>(x, in_ln_w, y, HIDDEN);

    // 2. merged qkv projection: rows 4096 q | 1024 k | 1024 v, K=2560 single chunk
    gemv3<false><<<dim3(148, 1), 256, 16 * (HIDDEN + 4) * 4>>>(
        q_w, k_w, v_w, q, k, v, 4096, 1024,
        N_HEADS * HD, N_KV * HD, N_KV * HD, y, HIDDEN, HIDDEN, 192);

    // 3-5. q/k norm+rope, v copy
    norm_rope_kernel<<<dim3(N_HEADS, T_NEW), HD>>>(q, q_norm_w, cos_q, sin_q, N_HEADS, q, nullptr, nullptr);
    norm_rope_kernel<<<dim3(N_KV, T_NEW), HD>>>(k, k_norm_w, cos_k, sin_k, N_KV, nullptr, knew, out_newk);
    vcopy_kernel<<<(N_KV * T_NEW * HD + 255) / 256, 256>>>(v, vnew, out_newv);

    // 6. residual pre-init h = x
    copy_kernel<<<(T_NEW * HIDDEN + 255) / 256, 256>>>(x, h, T_NEW * HIDDEN);

    // 7-10. attention
    zero_kernel<<<(T_NEW * N_HEADS * HD + 255) / 256, 256>>>(attn, T_NEW * N_HEADS * HD);
    scores_kernel<<<dim3(32, 8), 128, 128 * 129 * 4 + 4 * 2048 * 4>>>(cache_k, knew, q, scores);
    softmax_kernel<<<N_HEADS * T_NEW, 256>>>(scores);
    attnv_kernel<<<dim3(32, 8), 128, 128 * 128 * 4 + 128 * 16 * 4>>>(cache_v, vnew, scores, attn);

    // 11. o projection: K=4096, 2 chunks of 2048, atomic into h
    gemv3<true><<<dim3(80, 2), 256, 16 * (2048 + 4) * 4>>>(
        o_w, nullptr, nullptr, h, nullptr, nullptr, HIDDEN, 0,
        HIDDEN, 0, 0, attn, N_HEADS * HD, 2048, 80);

    // 12. post rmsnorm
    rmsnorm_kernel<<<T_NEW, 256>>>(h, post_ln_w, y2, HIDDEN);

    // 13. merged gate+up: rows 9728 | 9728, K=2560 single chunk
    gemv3<false><<<dim3(148, 1), 256, 16 * (HIDDEN + 4) * 4>>>(
        gate_w, up_w, nullptr, gg, uu, nullptr, INTER, INTER,
        INTER, INTER, 0, y2, HIDDEN, HIDDEN, 608);

    // 14. activation
    act_kernel<<<(T_NEW * INTER + 255) / 256, 256>>>(gg, uu, aa, T_NEW * INTER);

    // 15. residual pre-init out = h
    copy_kernel<<<(T_NEW * HIDDEN + 255) / 256, 256>>>(h, out_final, T_NEW * HIDDEN);

    // 16. down projection: K=9728, 4 chunks of 2432, atomic into out
    gemv3<true><<<dim3(80, 4), 256, 16 * (2432 + 4) * 4>>>(
        down_w, nullptr, nullptr, out_final, nullptr, nullptr, HIDDEN, 0,
        HIDDEN, 0, 0, aa, INTER, 2432, 80);

    (void)in_sizes; (void)n_in; (void)out_size;
}